// round 16
// baseline (speedup 1.0000x reference)
#include <cuda_runtime.h>
#include <cuda_fp16.h>
#include <cstdint>

// Problem sizes (fixed by the reference)
#define NNODES 50000
#define NREL   8
#define DIM    128
#define NEDGE  800000
#define NTRIP  100000
#define KTOT   1152          // NREL*DIM + DIM (root folded as 9th block)
#define K0LIM  1024          // NREL*DIM
#define NSEG   (NNODES * NREL)          // 400000
#define NBLK   ((NSEG + 1023) / 1024)   // 391

// ---------------- scratch (static device globals; no allocs allowed) -------
__device__ __align__(16) __half g_sum16[(size_t)NSEG * DIM];     // 102.4 MB fp16 means
__device__ __align__(16) __half g_e16[(size_t)NNODES * DIM];     // 12.8 MB emb fp16
__device__ __align__(16) __half g_h116[(size_t)NNODES * DIM];    // 12.8 MB
__device__ __align__(16) __half g_h216[(size_t)NNODES * DIM];    // 12.8 MB
__device__ __align__(16) __half g_WT016[(size_t)DIM * KTOT];     // (W0||root0)^T fp16
__device__ __align__(16) __half g_WT116[(size_t)DIM * KTOT];
__device__ int  g_cnt[NSEG];
__device__ int  g_off[NSEG];
__device__ __align__(8) int2 g_sr[NEDGE];   // (seg, rank) per edge, from hist
__device__ int  g_csr[NEDGE];
__device__ int  g_cursor;

__device__ __forceinline__ uint32_t smem_u32(const void* p) {
    uint32_t a;
    asm("{ .reg .u64 t; cvta.to.shared.u64 t, %1; cvt.u32.u64 %0, t; }"
        : "=r"(a) : "l"(p));
    return a;
}
__device__ __forceinline__ void cp16(uint32_t dst, const void* src, bool pred) {
    int sz = pred ? 16 : 0;
    asm volatile("cp.async.cg.shared.global [%0], [%1], 16, %2;"
                 :: "r"(dst), "l"(src), "r"(sz) : "memory");
}

// ---------------- fused prep: emb->fp16, W transpose, cnt zero -------------
#define PREP_CONV 3200            // conv blocks: 3200 x 256 thr x 2 uint2
#define PREP_TW   (2 * KTOT)      // 2304 transpose blocks
#define PREP_Z    391             // cnt-zero blocks
__global__ void prep_kernel(const float* __restrict__ emb,
                            const float* __restrict__ W0,
                            const float* __restrict__ root0,
                            const float* __restrict__ W1,
                            const float* __restrict__ root1) {
    int b = blockIdx.x;
    if (b < PREP_CONV) {
        const size_t n4 = (size_t)NNODES * DIM / 4;    // 1.6M uint2
        for (size_t i = (size_t)b * 512 + threadIdx.x;
             i < n4 && i < (size_t)(b + 1) * 512; i += 256) {
            float4 v = reinterpret_cast<const float4*>(emb)[i];
            __half2 lo = __floats2half2_rn(v.x, v.y);
            __half2 hi = __floats2half2_rn(v.z, v.w);
            uint2 o;
            o.x = *reinterpret_cast<uint32_t*>(&lo);
            o.y = *reinterpret_cast<uint32_t*>(&hi);
            reinterpret_cast<uint2*>(g_e16)[i] = o;
        }
    } else if (b < PREP_CONV + PREP_TW) {
        if (threadIdx.x < 128) {
            int bb = b - PREP_CONV;
            int layer = bb / KTOT;
            int k = bb % KTOT;
            const float* src;
            if (layer == 0)
                src = (k < K0LIM) ? (W0 + (size_t)k * DIM)
                                  : (root0 + (size_t)(k - K0LIM) * DIM);
            else
                src = (k < K0LIM) ? (W1 + (size_t)k * DIM)
                                  : (root1 + (size_t)(k - K0LIM) * DIM);
            float v = src[threadIdx.x];
            __half* dst = layer ? g_WT116 : g_WT016;
            dst[(size_t)threadIdx.x * KTOT + k] = __float2half_rn(v);
        }
    } else {
        int bb = b - PREP_CONV - PREP_TW;
        for (int i = bb * 1024 + threadIdx.x;
             i < NSEG && i < (bb + 1) * 1024; i += 256)
            g_cnt[i] = 0;
        if (bb == 0 && threadIdx.x == 0) g_cursor = 0;
    }
}

// ---------------- CSR build -----------------------------------------------
// hist: 4 edges/thread, interleaved atomics; persists packed (seg, rank).
__global__ void csr_hist(const int* __restrict__ ei,
                         const int* __restrict__ et) {
    int base = (blockIdx.x * blockDim.x + threadIdx.x) * 4;
    int seg[4];
#pragma unroll
    for (int j = 0; j < 4; ++j) {
        int e = base + j;
        seg[j] = (e < NEDGE) ? (ei[NEDGE + e] * NREL + et[e]) : -1;
    }
#pragma unroll
    for (int j = 0; j < 4; ++j)
        if (seg[j] >= 0) {
            int r = atomicAdd(&g_cnt[seg[j]], 1);
            g_sr[base + j] = make_int2(seg[j], r);
        }
}
// single-kernel offsets: in-block inclusive scan + atomic cursor for base.
__global__ void csr_off() {  // grid NBLK x 1024
    __shared__ int sh[1024];
    __shared__ int sbase;
    int gid = blockIdx.x * 1024 + threadIdx.x;
    int v = (gid < NSEG) ? g_cnt[gid] : 0;
    sh[threadIdx.x] = v;
    __syncthreads();
    for (int ofs = 1; ofs < 1024; ofs <<= 1) {
        int t = (threadIdx.x >= ofs) ? sh[threadIdx.x - ofs] : 0;
        __syncthreads();
        sh[threadIdx.x] += t;
        __syncthreads();
    }
    if (threadIdx.x == 1023) sbase = atomicAdd(&g_cursor, sh[1023]);
    __syncthreads();
    if (gid < NSEG) g_off[gid] = sbase + sh[threadIdx.x] - v;
}
// fill: atomic-free; one coalesced int2 load -> off gather -> scattered store.
__global__ void csr_fill(const int* __restrict__ ei) {
    int base = (blockIdx.x * blockDim.x + threadIdx.x) * 4;
    int2 sr[4];
    int src[4];
#pragma unroll
    for (int j = 0; j < 4; ++j) {
        int e = base + j;
        bool ok = (e < NEDGE);
        sr[j]  = ok ? g_sr[e] : make_int2(-1, 0);
        src[j] = ok ? ei[e] : 0;
    }
    int off[4];
#pragma unroll
    for (int j = 0; j < 4; ++j)
        off[j] = (sr[j].x >= 0) ? g_off[sr[j].x] : 0;
#pragma unroll
    for (int j = 0; j < 4; ++j)
        if (sr[j].x >= 0)
            g_csr[off[j] + sr[j].y] = src[j];
}

// ---------------- aggregate: 4 segments per warp, 2-deep batches -----------
__global__ __launch_bounds__(256) void aggregate_kernel(int useG) {
    int w    = (blockIdx.x * blockDim.x + threadIdx.x) >> 5;
    int lane = threadIdx.x & 31;
    int s0 = w * 4;
    if (s0 >= NSEG) return;
    const __half* __restrict__ h = useG ? g_h116 : g_e16;

    int beg[4], c[4];
    float4 acc[4];
#pragma unroll
    for (int j = 0; j < 4; ++j) {
        beg[j] = g_off[s0 + j];
        c[j]   = g_cnt[s0 + j];
        acc[j] = make_float4(0.f, 0.f, 0.f, 0.f);
    }
    int cmax = max(max(c[0], c[1]), max(c[2], c[3]));
    for (int base = 0; base < cmax; base += 2) {
        int idx[4][2];
#pragma unroll
        for (int j = 0; j < 4; ++j)
#pragma unroll
            for (int k = 0; k < 2; ++k)
                idx[j][k] = (base + k < c[j]) ? g_csr[beg[j] + base + k] : -1;
#pragma unroll
        for (int j = 0; j < 4; ++j)
#pragma unroll
            for (int k = 0; k < 2; ++k) {
                if (idx[j][k] >= 0) {
                    uint2 t = reinterpret_cast<const uint2*>(
                        h + (size_t)idx[j][k] * DIM)[lane];
                    float2 f0 = __half22float2(*reinterpret_cast<__half2*>(&t.x));
                    float2 f1 = __half22float2(*reinterpret_cast<__half2*>(&t.y));
                    acc[j].x += f0.x; acc[j].y += f0.y;
                    acc[j].z += f1.x; acc[j].w += f1.y;
                }
            }
    }
#pragma unroll
    for (int j = 0; j < 4; ++j) {
        float inv = 1.0f / (float)max(c[j], 1);
        __half2 o0 = __floats2half2_rn(acc[j].x * inv, acc[j].y * inv);
        __half2 o1 = __floats2half2_rn(acc[j].z * inv, acc[j].w * inv);
        uint2 r;
        r.x = *reinterpret_cast<uint32_t*>(&o0);
        r.y = *reinterpret_cast<uint32_t*>(&o1);
        reinterpret_cast<uint2*>(g_sum16 + (size_t)(s0 + j) * DIM)[lane] = r;
    }
}

// ---------------- fp16 mma.sync RGCN layer GEMM (cp.async pipeline) --------
// BM=128, BN=128, BK=64, 3-stage cp.async. 8 warps 4x2, warp tile 32x64.
#define KCH     64
#define NCHUNK  (KTOT / KCH)            // 18
#define LDPH    72                      // padded smem row stride (halfs)
#define BUF_H   (2 * 128 * LDPH)        // halfs per stage (A+B)
#define NSTAGE  3
#define SMEM_TOT (NSTAGE * BUF_H * 2)   // 110592 B

__device__ __forceinline__ void mma_f16(float* c, const uint32_t* a,
                                        const uint32_t* b) {
    asm volatile(
        "mma.sync.aligned.m16n8k16.row.col.f32.f16.f16.f32 "
        "{%0,%1,%2,%3}, {%4,%5,%6,%7}, {%8,%9}, {%0,%1,%2,%3};"
        : "+f"(c[0]), "+f"(c[1]), "+f"(c[2]), "+f"(c[3])
        : "r"(a[0]), "r"(a[1]), "r"(a[2]), "r"(a[3]), "r"(b[0]), "r"(b[1]));
}

__global__ __launch_bounds__(256, 2) void rgcn_gemm_mma(
    int useGin, int wtSel, const float* __restrict__ bias, int outSel)
{
    extern __shared__ __half smemh[];
    const uint32_t smemBase = smem_u32(smemh);
    const int tid  = threadIdx.x;
    const int wid  = tid >> 5;
    const int lane = tid & 31;
    const int g    = lane >> 2;
    const int t4   = lane & 3;
    const int wr   = wid & 3;        // warp row (M: 4 x 32)
    const int wc   = wid >> 2;       // warp col (N: 2 x 64)
    const int row0 = blockIdx.x * 128;

    const __half* __restrict__ hin = useGin ? g_h116 : g_e16;
    const __half* __restrict__ WT  = wtSel ? g_WT116 : g_WT016;
    __half* __restrict__ hout = outSel ? g_h216 : g_h116;

    float acc[2][8][4];
#pragma unroll
    for (int mt = 0; mt < 2; ++mt)
#pragma unroll
        for (int nt = 0; nt < 8; ++nt)
#pragma unroll
            for (int j = 0; j < 4; ++j) acc[mt][nt][j] = 0.f;

    auto issue = [&](int buf, int c) {
        const int k0 = c * KCH;
        const bool isSum = (k0 < K0LIM);
        uint32_t aBase = smemBase + (uint32_t)(buf * BUF_H) * 2u;
        uint32_t bBase = aBase + 128u * LDPH * 2u;
#pragma unroll
        for (int it = 0; it < 8; ++it) {
            int idx = tid + it * 256;        // 0..2047
            int m = (idx & 1023) >> 3;
            int q = idx & 7;
            uint32_t off = (uint32_t)(m * LDPH + q * 8) * 2u;
            if (idx < 1024) {
                int n = row0 + m;
                bool ok = (n < NNODES);
                int nc = ok ? n : (NNODES - 1);
                const __half* srcA = isSum
                    ? (g_sum16 + (size_t)nc * K0LIM + k0 + q * 8)
                    : (hin + (size_t)nc * DIM + (k0 - K0LIM) + q * 8);
                cp16(aBase + off, srcA, ok);
            } else {
                cp16(bBase + off, WT + (size_t)m * KTOT + k0 + q * 8, true);
            }
        }
        asm volatile("cp.async.commit_group;" ::: "memory");
    };

    auto compute = [&](int buf) {
        const __half* smA = smemh + buf * BUF_H;
        const __half* smB = smA + 128 * LDPH;
#pragma unroll
        for (int ks = 0; ks < 4; ++ks) {
            const int kk = ks * 16;
            uint32_t a[2][4], b[8][2];
#pragma unroll
            for (int mt = 0; mt < 2; ++mt) {
                int r0 = wr * 32 + mt * 16 + g;
                a[mt][0] = *reinterpret_cast<const uint32_t*>(
                    smA + (r0)     * LDPH + kk + 2 * t4);
                a[mt][1] = *reinterpret_cast<const uint32_t*>(
                    smA + (r0 + 8) * LDPH + kk + 2 * t4);
                a[mt][2] = *reinterpret_cast<const uint32_t*>(
                    smA + (r0)     * LDPH + kk + 8 + 2 * t4);
                a[mt][3] = *reinterpret_cast<const uint32_t*>(
                    smA + (r0 + 8) * LDPH + kk + 8 + 2 * t4);
            }
#pragma unroll
            for (int nt = 0; nt < 8; ++nt) {
                int nn = wc * 64 + nt * 8 + g;
                b[nt][0] = *reinterpret_cast<const uint32_t*>(
                    smB + nn * LDPH + kk + 2 * t4);
                b[nt][1] = *reinterpret_cast<const uint32_t*>(
                    smB + nn * LDPH + kk + 8 + 2 * t4);
            }
#pragma unroll
            for (int mt = 0; mt < 2; ++mt)
#pragma unroll
                for (int nt = 0; nt < 8; ++nt)
                    mma_f16(acc[mt][nt], a[mt], b[nt]);
        }
    };

    issue(0, 0);
    issue(1, 1);
    for (int c = 0; c < NCHUNK; ++c) {
        if (c + 2 < NCHUNK) {
            issue((c + 2) % NSTAGE, c + 2);
            asm volatile("cp.async.wait_group 2;" ::: "memory");
        } else if (c + 1 < NCHUNK) {
            asm volatile("cp.async.wait_group 1;" ::: "memory");
        } else {
            asm volatile("cp.async.wait_group 0;" ::: "memory");
        }
        __syncthreads();
        compute(c % NSTAGE);
        __syncthreads();
    }

    // ---- epilogue: bias + relu, write fp16 ----
    float2 bb[8];
#pragma unroll
    for (int nt = 0; nt < 8; ++nt) {
        int col = wc * 64 + nt * 8 + t4 * 2;
        bb[nt].x = __ldg(bias + col);
        bb[nt].y = __ldg(bias + col + 1);
    }
#pragma unroll
    for (int mt = 0; mt < 2; ++mt) {
        int r0 = row0 + wr * 32 + mt * 16 + g;
#pragma unroll
        for (int half = 0; half < 2; ++half) {
            int n = r0 + half * 8;
            if (n < NNODES) {
                __half* dst = hout + (size_t)n * DIM;
#pragma unroll
                for (int nt = 0; nt < 8; ++nt) {
                    int col = wc * 64 + nt * 8 + t4 * 2;
                    float ox = fmaxf(acc[mt][nt][half * 2 + 0] + bb[nt].x, 0.f);
                    float oy = fmaxf(acc[mt][nt][half * 2 + 1] + bb[nt].y, 0.f);
                    *reinterpret_cast<__half2*>(dst + col) =
                        __floats2half2_rn(ox, oy);
                }
            }
        }
    }
}

// ---------------- DistMult score: 4 triples per warp (fp16 h) --------------
__global__ void score_kernel(const float* __restrict__ rel_emb,
                             const int* __restrict__ head,
                             const int* __restrict__ rel,
                             const int* __restrict__ tail,
                             float* __restrict__ out) {
    int w    = (blockIdx.x * blockDim.x + threadIdx.x) >> 5;
    int lane = threadIdx.x & 31;
    int t0 = w * 4;
    if (t0 >= NTRIP) return;

    int tt[4], hh[4], ll[4], rr[4];
#pragma unroll
    for (int j = 0; j < 4; ++j) {
        tt[j] = min(t0 + j, NTRIP - 1);
        hh[j] = head[tt[j]];
        ll[j] = tail[tt[j]];
        rr[j] = rel[tt[j]];
    }
    uint2 ar[4], br[4];
    float4 rv[4];
#pragma unroll
    for (int j = 0; j < 4; ++j) {
        ar[j] = reinterpret_cast<const uint2*>(g_h216 + (size_t)hh[j] * DIM)[lane];
        br[j] = reinterpret_cast<const uint2*>(g_h216 + (size_t)ll[j] * DIM)[lane];
        rv[j] = reinterpret_cast<const float4*>(rel_emb + (size_t)rr[j] * DIM)[lane];
    }
    float s[4];
#pragma unroll
    for (int j = 0; j < 4; ++j) {
        float2 a0 = __half22float2(*reinterpret_cast<__half2*>(&ar[j].x));
        float2 a1 = __half22float2(*reinterpret_cast<__half2*>(&ar[j].y));
        float2 b0 = __half22float2(*reinterpret_cast<__half2*>(&br[j].x));
        float2 b1 = __half22float2(*reinterpret_cast<__half2*>(&br[j].y));
        s[j] = a0.x * rv[j].x * b0.x + a0.y * rv[j].y * b0.y
             + a1.x * rv[j].z * b1.x + a1.y * rv[j].w * b1.y;
    }
#pragma unroll
    for (int off = 16; off; off >>= 1)
#pragma unroll
        for (int j = 0; j < 4; ++j)
            s[j] += __shfl_xor_sync(0xFFFFFFFFu, s[j], off);
    if (lane == 0) {
#pragma unroll
        for (int j = 0; j < 4; ++j)
            if (t0 + j < NTRIP) out[t0 + j] = s[j];
    }
}

// ---------------- launcher -------------------------------------------------
extern "C" void kernel_launch(void* const* d_in, const int* in_sizes, int n_in,
                              void* d_out, int out_size) {
    const float* emb   = (const float*)d_in[0];
    const float* W0    = (const float*)d_in[1];
    const float* root0 = (const float*)d_in[2];
    const float* b0    = (const float*)d_in[3];
    const float* W1    = (const float*)d_in[4];
    const float* root1 = (const float*)d_in[5];
    const float* b1    = (const float*)d_in[6];
    const float* relE  = (const float*)d_in[7];
    const int*   ei    = (const int*)d_in[8];
    const int*   et    = (const int*)d_in[9];
    const int*   hidx  = (const int*)d_in[10];
    const int*   ridx  = (const int*)d_in[11];
    const int*   tidx  = (const int*)d_in[12];
    float*       out   = (float*)d_out;

    static int smemSet = 0;
    if (!smemSet) {
        cudaFuncSetAttribute(rgcn_gemm_mma,
                             cudaFuncAttributeMaxDynamicSharedMemorySize,
                             SMEM_TOT);
        smemSet = 1;
    }

    const int prepGrid  = PREP_CONV + PREP_TW + PREP_Z;       // 5895
    const int edgeGrid4 = (NEDGE + 1023) / 1024;              // 782 (4 edges/thr)
    const int aggGrid   = ((NSEG / 4) * 32 + 255) / 256;      // 12500
    const int gemmGrid  = (NNODES + 127) / 128;               // 391
    const int scoreGrid = (((NTRIP + 3) / 4) * 32 + 255) / 256; // 3125

    prep_kernel<<<prepGrid, 256>>>(emb, W0, root0, W1, root1);

    // ----- CSR build (shared by both layers) -----
    csr_hist<<<edgeGrid4, 256>>>(ei, et);
    csr_off<<<NBLK, 1024>>>();
    csr_fill<<<edgeGrid4, 256>>>(ei);

    // ----- layer 0 -----
    aggregate_kernel<<<aggGrid, 256>>>(0);
    rgcn_gemm_mma<<<gemmGrid, 256, SMEM_TOT>>>(0, /*wt*/0, b0, /*out*/0);

    // ----- layer 1 -----
    aggregate_kernel<<<aggGrid, 256>>>(1);
    rgcn_gemm_mma<<<gemmGrid, 256, SMEM_TOT>>>(1, /*wt*/1, b1, /*out*/1);

    // ----- DistMult score -----
    score_kernel<<<scoreGrid, 256>>>(relE, hidx, ridx, tidx, out);
}

// round 17
// speedup vs baseline: 1.0217x; 1.0217x over previous
#include <cuda_runtime.h>
#include <cuda_fp16.h>
#include <cstdint>

// Problem sizes (fixed by the reference)
#define NNODES 50000
#define NREL   8
#define DIM    128
#define NEDGE  800000
#define NTRIP  100000
#define KTOT   1152          // NREL*DIM + DIM (root folded as 9th block)
#define K0LIM  1024          // NREL*DIM
#define NSEG   (NNODES * NREL)          // 400000
#define NBLK   ((NSEG + 1023) / 1024)   // 391

// ---------------- scratch (static device globals; no allocs allowed) -------
__device__ __align__(16) __half g_sum16[(size_t)NSEG * DIM];     // 102.4 MB fp16 means
__device__ __align__(16) __half g_e16[(size_t)NNODES * DIM];     // 12.8 MB emb fp16
__device__ __align__(16) __half g_h116[(size_t)NNODES * DIM];    // 12.8 MB
__device__ __align__(16) __half g_h216[(size_t)NNODES * DIM];    // 12.8 MB
__device__ __align__(16) __half g_WT016[(size_t)DIM * KTOT];     // (W0||root0)^T fp16
__device__ __align__(16) __half g_WT116[(size_t)DIM * KTOT];
__device__ int g_cnt[NSEG];
__device__ int g_off[NSEG];
__device__ int g_fill[NSEG];
__device__ int g_csr[NEDGE];
__device__ int g_cursor;

__device__ __forceinline__ uint32_t smem_u32(const void* p) {
    uint32_t a;
    asm("{ .reg .u64 t; cvta.to.shared.u64 t, %1; cvt.u32.u64 %0, t; }"
        : "=r"(a) : "l"(p));
    return a;
}
__device__ __forceinline__ void cp16(uint32_t dst, const void* src, bool pred) {
    int sz = pred ? 16 : 0;
    asm volatile("cp.async.cg.shared.global [%0], [%1], 16, %2;"
                 :: "r"(dst), "l"(src), "r"(sz) : "memory");
}

// ---------------- zero cnt (needed before hist; tiny, main stream) ---------
__global__ void zero_cnt() {
    for (int i = blockIdx.x * 1024 + threadIdx.x;
         i < NSEG && i < (blockIdx.x + 1) * 1024; i += 256)
        g_cnt[i] = 0;
    if (blockIdx.x == 0 && threadIdx.x == 0) g_cursor = 0;
}

// ---------------- side-stream prep: emb->fp16 + W transpose ----------------
#define PREP_CONV 3200            // conv blocks: 3200 x 256 thr x 2 uint2
#define PREP_TW   (2 * KTOT)      // 2304 transpose blocks
__global__ void prep_conv_tw(const float* __restrict__ emb,
                             const float* __restrict__ W0,
                             const float* __restrict__ root0,
                             const float* __restrict__ W1,
                             const float* __restrict__ root1) {
    int b = blockIdx.x;
    if (b < PREP_CONV) {
        const size_t n4 = (size_t)NNODES * DIM / 4;    // 1.6M uint2
        for (size_t i = (size_t)b * 512 + threadIdx.x;
             i < n4 && i < (size_t)(b + 1) * 512; i += 256) {
            float4 v = reinterpret_cast<const float4*>(emb)[i];
            __half2 lo = __floats2half2_rn(v.x, v.y);
            __half2 hi = __floats2half2_rn(v.z, v.w);
            uint2 o;
            o.x = *reinterpret_cast<uint32_t*>(&lo);
            o.y = *reinterpret_cast<uint32_t*>(&hi);
            reinterpret_cast<uint2*>(g_e16)[i] = o;
        }
    } else {
        if (threadIdx.x < 128) {
            int bb = b - PREP_CONV;
            int layer = bb / KTOT;
            int k = bb % KTOT;
            const float* src;
            if (layer == 0)
                src = (k < K0LIM) ? (W0 + (size_t)k * DIM)
                                  : (root0 + (size_t)(k - K0LIM) * DIM);
            else
                src = (k < K0LIM) ? (W1 + (size_t)k * DIM)
                                  : (root1 + (size_t)(k - K0LIM) * DIM);
            float v = src[threadIdx.x];
            __half* dst = layer ? g_WT116 : g_WT016;
            dst[(size_t)threadIdx.x * KTOT + k] = __float2half_rn(v);
        }
    }
}

// ---------------- CSR build (R14-proven versions) --------------------------
__global__ void csr_hist(const int* __restrict__ ei,
                         const int* __restrict__ et) {
    int e = blockIdx.x * blockDim.x + threadIdx.x;
    if (e >= NEDGE) return;
    int seg = ei[NEDGE + e] * NREL + et[e];
    atomicAdd(&g_cnt[seg], 1);
}
// single-kernel offsets: in-block inclusive scan + atomic cursor for base.
// Also zeroes g_fill (touches the same indices anyway).
__global__ void csr_off() {  // grid NBLK x 1024
    __shared__ int sh[1024];
    __shared__ int sbase;
    int gid = blockIdx.x * 1024 + threadIdx.x;
    int v = (gid < NSEG) ? g_cnt[gid] : 0;
    sh[threadIdx.x] = v;
    __syncthreads();
    for (int ofs = 1; ofs < 1024; ofs <<= 1) {
        int t = (threadIdx.x >= ofs) ? sh[threadIdx.x - ofs] : 0;
        __syncthreads();
        sh[threadIdx.x] += t;
        __syncthreads();
    }
    if (threadIdx.x == 1023) sbase = atomicAdd(&g_cursor, sh[1023]);
    __syncthreads();
    if (gid < NSEG) {
        g_off[gid] = sbase + sh[threadIdx.x] - v;
        g_fill[gid] = 0;
    }
}
__global__ void csr_fill(const int* __restrict__ ei,
                         const int* __restrict__ et) {
    int e = blockIdx.x * blockDim.x + threadIdx.x;
    if (e >= NEDGE) return;
    int seg = ei[NEDGE + e] * NREL + et[e];
    int pos = g_off[seg] + atomicAdd(&g_fill[seg], 1);
    g_csr[pos] = ei[e];
}

// ---------------- aggregate: 4 segments per warp, 2-deep batches -----------
__global__ __launch_bounds__(256) void aggregate_kernel(int useG) {
    int w    = (blockIdx.x * blockDim.x + threadIdx.x) >> 5;
    int lane = threadIdx.x & 31;
    int s0 = w * 4;
    if (s0 >= NSEG) return;
    const __half* __restrict__ h = useG ? g_h116 : g_e16;

    int beg[4], c[4];
    float4 acc[4];
#pragma unroll
    for (int j = 0; j < 4; ++j) {
        beg[j] = g_off[s0 + j];
        c[j]   = g_cnt[s0 + j];
        acc[j] = make_float4(0.f, 0.f, 0.f, 0.f);
    }
    int cmax = max(max(c[0], c[1]), max(c[2], c[3]));
    for (int base = 0; base < cmax; base += 2) {
        int idx[4][2];
#pragma unroll
        for (int j = 0; j < 4; ++j)
#pragma unroll
            for (int k = 0; k < 2; ++k)
                idx[j][k] = (base + k < c[j]) ? g_csr[beg[j] + base + k] : -1;
#pragma unroll
        for (int j = 0; j < 4; ++j)
#pragma unroll
            for (int k = 0; k < 2; ++k) {
                if (idx[j][k] >= 0) {
                    uint2 t = reinterpret_cast<const uint2*>(
                        h + (size_t)idx[j][k] * DIM)[lane];
                    float2 f0 = __half22float2(*reinterpret_cast<__half2*>(&t.x));
                    float2 f1 = __half22float2(*reinterpret_cast<__half2*>(&t.y));
                    acc[j].x += f0.x; acc[j].y += f0.y;
                    acc[j].z += f1.x; acc[j].w += f1.y;
                }
            }
    }
#pragma unroll
    for (int j = 0; j < 4; ++j) {
        float inv = 1.0f / (float)max(c[j], 1);
        __half2 o0 = __floats2half2_rn(acc[j].x * inv, acc[j].y * inv);
        __half2 o1 = __floats2half2_rn(acc[j].z * inv, acc[j].w * inv);
        uint2 r;
        r.x = *reinterpret_cast<uint32_t*>(&o0);
        r.y = *reinterpret_cast<uint32_t*>(&o1);
        reinterpret_cast<uint2*>(g_sum16 + (size_t)(s0 + j) * DIM)[lane] = r;
    }
}

// ---------------- fp16 mma.sync RGCN layer GEMM (cp.async pipeline) --------
// BM=128, BN=128, BK=64, 3-stage cp.async. 8 warps 4x2, warp tile 32x64.
#define KCH     64
#define NCHUNK  (KTOT / KCH)            // 18
#define LDPH    72                      // padded smem row stride (halfs)
#define BUF_H   (2 * 128 * LDPH)        // halfs per stage (A+B)
#define NSTAGE  3
#define SMEM_TOT (NSTAGE * BUF_H * 2)   // 110592 B

__device__ __forceinline__ void mma_f16(float* c, const uint32_t* a,
                                        const uint32_t* b) {
    asm volatile(
        "mma.sync.aligned.m16n8k16.row.col.f32.f16.f16.f32 "
        "{%0,%1,%2,%3}, {%4,%5,%6,%7}, {%8,%9}, {%0,%1,%2,%3};"
        : "+f"(c[0]), "+f"(c[1]), "+f"(c[2]), "+f"(c[3])
        : "r"(a[0]), "r"(a[1]), "r"(a[2]), "r"(a[3]), "r"(b[0]), "r"(b[1]));
}

__global__ __launch_bounds__(256, 2) void rgcn_gemm_mma(
    int useGin, int wtSel, const float* __restrict__ bias, int outSel)
{
    extern __shared__ __half smemh[];
    const uint32_t smemBase = smem_u32(smemh);
    const int tid  = threadIdx.x;
    const int wid  = tid >> 5;
    const int lane = tid & 31;
    const int g    = lane >> 2;
    const int t4   = lane & 3;
    const int wr   = wid & 3;        // warp row (M: 4 x 32)
    const int wc   = wid >> 2;       // warp col (N: 2 x 64)
    const int row0 = blockIdx.x * 128;

    const __half* __restrict__ hin = useGin ? g_h116 : g_e16;
    const __half* __restrict__ WT  = wtSel ? g_WT116 : g_WT016;
    __half* __restrict__ hout = outSel ? g_h216 : g_h116;

    float acc[2][8][4];
#pragma unroll
    for (int mt = 0; mt < 2; ++mt)
#pragma unroll
        for (int nt = 0; nt < 8; ++nt)
#pragma unroll
            for (int j = 0; j < 4; ++j) acc[mt][nt][j] = 0.f;

    auto issue = [&](int buf, int c) {
        const int k0 = c * KCH;
        const bool isSum = (k0 < K0LIM);
        uint32_t aBase = smemBase + (uint32_t)(buf * BUF_H) * 2u;
        uint32_t bBase = aBase + 128u * LDPH * 2u;
#pragma unroll
        for (int it = 0; it < 8; ++it) {
            int idx = tid + it * 256;        // 0..2047
            int m = (idx & 1023) >> 3;
            int q = idx & 7;
            uint32_t off = (uint32_t)(m * LDPH + q * 8) * 2u;
            if (idx < 1024) {
                int n = row0 + m;
                bool ok = (n < NNODES);
                int nc = ok ? n : (NNODES - 1);
                const __half* srcA = isSum
                    ? (g_sum16 + (size_t)nc * K0LIM + k0 + q * 8)
                    : (hin + (size_t)nc * DIM + (k0 - K0LIM) + q * 8);
                cp16(aBase + off, srcA, ok);
            } else {
                cp16(bBase + off, WT + (size_t)m * KTOT + k0 + q * 8, true);
            }
        }
        asm volatile("cp.async.commit_group;" ::: "memory");
    };

    auto compute = [&](int buf) {
        const __half* smA = smemh + buf * BUF_H;
        const __half* smB = smA + 128 * LDPH;
#pragma unroll
        for (int ks = 0; ks < 4; ++ks) {
            const int kk = ks * 16;
            uint32_t a[2][4], b[8][2];
#pragma unroll
            for (int mt = 0; mt < 2; ++mt) {
                int r0 = wr * 32 + mt * 16 + g;
                a[mt][0] = *reinterpret_cast<const uint32_t*>(
                    smA + (r0)     * LDPH + kk + 2 * t4);
                a[mt][1] = *reinterpret_cast<const uint32_t*>(
                    smA + (r0 + 8) * LDPH + kk + 2 * t4);
                a[mt][2] = *reinterpret_cast<const uint32_t*>(
                    smA + (r0)     * LDPH + kk + 8 + 2 * t4);
                a[mt][3] = *reinterpret_cast<const uint32_t*>(
                    smA + (r0 + 8) * LDPH + kk + 8 + 2 * t4);
            }
#pragma unroll
            for (int nt = 0; nt < 8; ++nt) {
                int nn = wc * 64 + nt * 8 + g;
                b[nt][0] = *reinterpret_cast<const uint32_t*>(
                    smB + nn * LDPH + kk + 2 * t4);
                b[nt][1] = *reinterpret_cast<const uint32_t*>(
                    smB + nn * LDPH + kk + 8 + 2 * t4);
            }
#pragma unroll
            for (int mt = 0; mt < 2; ++mt)
#pragma unroll
                for (int nt = 0; nt < 8; ++nt)
                    mma_f16(acc[mt][nt], a[mt], b[nt]);
        }
    };

    issue(0, 0);
    issue(1, 1);
    for (int c = 0; c < NCHUNK; ++c) {
        if (c + 2 < NCHUNK) {
            issue((c + 2) % NSTAGE, c + 2);
            asm volatile("cp.async.wait_group 2;" ::: "memory");
        } else if (c + 1 < NCHUNK) {
            asm volatile("cp.async.wait_group 1;" ::: "memory");
        } else {
            asm volatile("cp.async.wait_group 0;" ::: "memory");
        }
        __syncthreads();
        compute(c % NSTAGE);
        __syncthreads();
    }

    // ---- epilogue: bias + relu, write fp16 ----
    float2 bb[8];
#pragma unroll
    for (int nt = 0; nt < 8; ++nt) {
        int col = wc * 64 + nt * 8 + t4 * 2;
        bb[nt].x = __ldg(bias + col);
        bb[nt].y = __ldg(bias + col + 1);
    }
#pragma unroll
    for (int mt = 0; mt < 2; ++mt) {
        int r0 = row0 + wr * 32 + mt * 16 + g;
#pragma unroll
        for (int half = 0; half < 2; ++half) {
            int n = r0 + half * 8;
            if (n < NNODES) {
                __half* dst = hout + (size_t)n * DIM;
#pragma unroll
                for (int nt = 0; nt < 8; ++nt) {
                    int col = wc * 64 + nt * 8 + t4 * 2;
                    float ox = fmaxf(acc[mt][nt][half * 2 + 0] + bb[nt].x, 0.f);
                    float oy = fmaxf(acc[mt][nt][half * 2 + 1] + bb[nt].y, 0.f);
                    *reinterpret_cast<__half2*>(dst + col) =
                        __floats2half2_rn(ox, oy);
                }
            }
        }
    }
}

// ---------------- DistMult score: 2 triples per warp (fp16 h) --------------
__global__ void score_kernel(const float* __restrict__ rel_emb,
                             const int* __restrict__ head,
                             const int* __restrict__ rel,
                             const int* __restrict__ tail,
                             float* __restrict__ out) {
    int w    = (blockIdx.x * blockDim.x + threadIdx.x) >> 5;
    int lane = threadIdx.x & 31;
    int t0 = w * 2;
    if (t0 >= NTRIP) return;
    int t1 = min(t0 + 1, NTRIP - 1);

    int h0 = head[t0], h1 = head[t1];
    int l0 = tail[t0], l1 = tail[t1];
    int r0i = rel[t0],  r1i = rel[t1];

    uint2 a0r = reinterpret_cast<const uint2*>(g_h216 + (size_t)h0 * DIM)[lane];
    uint2 a1r = reinterpret_cast<const uint2*>(g_h216 + (size_t)h1 * DIM)[lane];
    uint2 b0r = reinterpret_cast<const uint2*>(g_h216 + (size_t)l0 * DIM)[lane];
    uint2 b1r = reinterpret_cast<const uint2*>(g_h216 + (size_t)l1 * DIM)[lane];
    float4 r0 = reinterpret_cast<const float4*>(rel_emb + (size_t)r0i * DIM)[lane];
    float4 r1 = reinterpret_cast<const float4*>(rel_emb + (size_t)r1i * DIM)[lane];

    float2 a00 = __half22float2(*reinterpret_cast<__half2*>(&a0r.x));
    float2 a01 = __half22float2(*reinterpret_cast<__half2*>(&a0r.y));
    float2 b00 = __half22float2(*reinterpret_cast<__half2*>(&b0r.x));
    float2 b01 = __half22float2(*reinterpret_cast<__half2*>(&b0r.y));
    float2 a10 = __half22float2(*reinterpret_cast<__half2*>(&a1r.x));
    float2 a11 = __half22float2(*reinterpret_cast<__half2*>(&a1r.y));
    float2 b10 = __half22float2(*reinterpret_cast<__half2*>(&b1r.x));
    float2 b11 = __half22float2(*reinterpret_cast<__half2*>(&b1r.y));

    float s0 = a00.x * r0.x * b00.x + a00.y * r0.y * b00.y
             + a01.x * r0.z * b01.x + a01.y * r0.w * b01.y;
    float s1 = a10.x * r1.x * b10.x + a10.y * r1.y * b10.y
             + a11.x * r1.z * b11.x + a11.y * r1.w * b11.y;
#pragma unroll
    for (int off = 16; off; off >>= 1) {
        s0 += __shfl_xor_sync(0xFFFFFFFFu, s0, off);
        s1 += __shfl_xor_sync(0xFFFFFFFFu, s1, off);
    }
    if (lane == 0) {
        out[t0] = s0;
        if (t1 > t0) out[t1] = s1;
    }
}

// ---------------- launcher -------------------------------------------------
extern "C" void kernel_launch(void* const* d_in, const int* in_sizes, int n_in,
                              void* d_out, int out_size) {
    const float* emb   = (const float*)d_in[0];
    const float* W0    = (const float*)d_in[1];
    const float* root0 = (const float*)d_in[2];
    const float* b0    = (const float*)d_in[3];
    const float* W1    = (const float*)d_in[4];
    const float* root1 = (const float*)d_in[5];
    const float* b1    = (const float*)d_in[6];
    const float* relE  = (const float*)d_in[7];
    const int*   ei    = (const int*)d_in[8];
    const int*   et    = (const int*)d_in[9];
    const int*   hidx  = (const int*)d_in[10];
    const int*   ridx  = (const int*)d_in[11];
    const int*   tidx  = (const int*)d_in[12];
    float*       out   = (float*)d_out;

    static cudaStream_t s2 = nullptr;
    static cudaEvent_t evFork = nullptr, evJoin = nullptr;
    static int inited = 0;
    if (!inited) {
        cudaFuncSetAttribute(rgcn_gemm_mma,
                             cudaFuncAttributeMaxDynamicSharedMemorySize,
                             SMEM_TOT);
        cudaStreamCreateWithFlags(&s2, cudaStreamNonBlocking);
        cudaEventCreateWithFlags(&evFork, cudaEventDisableTiming);
        cudaEventCreateWithFlags(&evJoin, cudaEventDisableTiming);
        inited = 1;
    }

    const int edgeGrid  = (NEDGE + 255) / 256;               // 3125
    const int aggGrid   = ((NSEG / 4) * 32 + 255) / 256;     // 12500
    const int gemmGrid  = (NNODES + 127) / 128;              // 391
    const int scoreGrid = (((NTRIP + 1) / 2) * 32 + 255) / 256; // 6250

    // main stream: zero counts (hist dependency), then fork side stream
    zero_cnt<<<NBLK, 256>>>();
    cudaEventRecord(evFork, 0);
    cudaStreamWaitEvent(s2, evFork, 0);

    // side stream: emb->fp16 + W transpose (needed only by agg/gemm)
    prep_conv_tw<<<PREP_CONV + PREP_TW, 256, 0, s2>>>(emb, W0, root0, W1, root1);
    cudaEventRecord(evJoin, s2);

    // main stream: CSR build (overlaps with side-stream prep)
    csr_hist<<<edgeGrid, 256>>>(ei, et);
    csr_off<<<NBLK, 1024>>>();
    csr_fill<<<edgeGrid, 256>>>(ei, et);

    // join: agg needs g_e16, gemm needs WT
    cudaStreamWaitEvent(0, evJoin, 0);

    // ----- layer 0 -----
    aggregate_kernel<<<aggGrid, 256>>>(0);
    rgcn_gemm_mma<<<gemmGrid, 256, SMEM_TOT>>>(0, /*wt*/0, b0, /*out*/0);

    // ----- layer 1 -----
    aggregate_kernel<<<aggGrid, 256>>>(1);
    rgcn_gemm_mma<<<gemmGrid, 256, SMEM_TOT>>>(1, /*wt*/1, b1, /*out*/1);

    // ----- DistMult score -----
    score_kernel<<<scoreGrid, 256>>>(relE, hidx, ridx, tidx, out);
}